// round 17
// baseline (speedup 1.0000x reference)
#include <cuda_runtime.h>

#define N_NODES 8192
#define NV8 (N_NODES / 8)       // 1024 v8-groups per row
#define PSI 64
#define GRID_RS 1184            // 148 SMs x 8 blocks, grid-stride over rows
#define PREFETCH_ROWS 1024      // 32 MB warmed into L2 during the scatter phase

// __device__ scratch (no allocations allowed).
// g_agg zero-init at load; node_mlp reads-then-zeros it each replay.
// g_t is 32B-aligned for 256-bit loads.
__device__ float g_agg[N_NODES];
__device__ __align__(32) float g_t[N_NODES];
__device__ float g_s[N_NODES];
__device__ float g_sink;        // prefetch DCE guard (never actually written)

// 256-bit global loads (sm_100a: LDG.E.256)
__device__ __forceinline__ void ldg256_cs(const float* __restrict__ p, float r[8]) {
    asm volatile("ld.global.cs.v8.f32 {%0,%1,%2,%3,%4,%5,%6,%7}, [%8];"
        : "=f"(r[0]), "=f"(r[1]), "=f"(r[2]), "=f"(r[3]),
          "=f"(r[4]), "=f"(r[5]), "=f"(r[6]), "=f"(r[7])
        : "l"(p));
}
__device__ __forceinline__ void ldg256_nc(const float* __restrict__ p, float r[8]) {
    asm volatile("ld.global.nc.v8.f32 {%0,%1,%2,%3,%4,%5,%6,%7}, [%8];"
        : "=f"(r[0]), "=f"(r[1]), "=f"(r[2]), "=f"(r[3]),
          "=f"(r[4]), "=f"(r[5]), "=f"(r[6]), "=f"(r[7])
        : "l"(p));
}

// ---------------------------------------------------------------------------
// Kernel 0: L2 prefetch of the first PREFETCH_ROWS rows of adj.
// Triggers programmatic completion IMMEDIATELY so the (independent)
// edge_scatter launched behind it starts concurrently.
// ---------------------------------------------------------------------------
__global__ __launch_bounds__(256) void k_prefetch(const float* __restrict__ adj) {
    cudaTriggerProgrammaticLaunchCompletion();   // release the next kernel now
    const float4* __restrict__ a = reinterpret_cast<const float4*>(adj);
    const int total = PREFETCH_ROWS * (N_NODES / 4);
    float acc = 0.0f;
    for (int i = blockIdx.x * 256 + threadIdx.x; i < total; i += 512 * 256) {
        float4 v = __ldcg(&a[i]);                // L2-allocating load
        acc += v.x + v.y + v.z + v.w;
    }
    if (acc == -1.2345678e-33f) g_sink = acc;    // keep the loads alive
}

// ---------------------------------------------------------------------------
// Kernel 1: edge MLP + scatter-add by col.
// Algebraic fast path (zero hidden bias, verified on device):
//   f(v) = v*Cp + b2  (v >= 0),   f(v) = v*Cn + b2  (v < 0).
// Generic 64-term fallback keeps the kernel exact for arbitrary inputs.
// ---------------------------------------------------------------------------
__global__ __launch_bounds__(256) void k_edge_scatter(
        const int* __restrict__ col,
        const float* __restrict__ values,
        const float* __restrict__ w1,
        const float* __restrict__ b1,
        const float* __restrict__ w2,
        const float* __restrict__ b2,
        int nnz) {
    __shared__ float sw1[PSI], sb1[PSI], sw2[PSI];
    __shared__ float sCp, sCn, sb2;
    __shared__ int sfast;
    if (threadIdx.x < PSI) {
        sw1[threadIdx.x] = w1[threadIdx.x];
        sb1[threadIdx.x] = b1[threadIdx.x];
        sw2[threadIdx.x] = w2[threadIdx.x];
    }
    if (threadIdx.x == 0) sb2 = b2[0];
    __syncthreads();
    if (threadIdx.x == 0) {
        float cp = 0.0f, cn = 0.0f;
        int ok = 1;
#pragma unroll
        for (int j = 0; j < PSI; j++) {
            float w = sw1[j];
            float p = w * sw2[j];
            if (w > 0.0f) cp += p;
            else if (w < 0.0f) cn += p;
            if (sb1[j] != 0.0f) ok = 0;
        }
        sCp = cp; sCn = cn; sfast = ok;
    }
    __syncthreads();

    int i = blockIdx.x * 256 + threadIdx.x;
    if (i >= nnz) return;
    float v = values[i];
    float feat;
    if (sfast) {
        feat = fmaf(v, (v >= 0.0f) ? sCp : sCn, sb2);
    } else {
        float p0 = 0.0f, p1 = 0.0f, p2 = 0.0f, p3 = 0.0f;
#pragma unroll
        for (int j = 0; j < PSI; j += 4) {
            p0 = fmaf(fmaxf(fmaf(v, sw1[j+0], sb1[j+0]), 0.0f), sw2[j+0], p0);
            p1 = fmaf(fmaxf(fmaf(v, sw1[j+1], sb1[j+1]), 0.0f), sw2[j+1], p1);
            p2 = fmaf(fmaxf(fmaf(v, sw1[j+2], sb1[j+2]), 0.0f), sw2[j+2], p2);
            p3 = fmaf(fmaxf(fmaf(v, sw1[j+3], sb1[j+3]), 0.0f), sw2[j+3], p3);
        }
        feat = sb2 + (p0 + p1) + (p2 + p3);
    }
    atomicAdd(&g_agg[col[i]], feat);
}

// ---------------------------------------------------------------------------
// Kernel 2: node MLP, store struct^2, re-zero g_agg for the next replay.
// PDL secondary (waits on edge_scatter).
// ---------------------------------------------------------------------------
__global__ __launch_bounds__(512) void k_node_mlp(
        const float* __restrict__ w1,
        const float* __restrict__ b1,
        const float* __restrict__ w2,
        const float* __restrict__ b2) {
    __shared__ float sw1[PSI], sb1[PSI], sw2[PSI], sb2;
    if (threadIdx.x < PSI) {
        sw1[threadIdx.x] = w1[threadIdx.x];
        sb1[threadIdx.x] = b1[threadIdx.x];
        sw2[threadIdx.x] = w2[threadIdx.x];
    }
    if (threadIdx.x == 0) sb2 = b2[0];
    __syncthreads();

    cudaGridDependencySynchronize();   // all g_agg atomics visible

    int i = blockIdx.x * 512 + threadIdx.x;
    if (i >= N_NODES) return;
    float x = g_agg[i];
    g_agg[i] = 0.0f;              // reset for next graph replay
    float p0 = 0.0f, p1 = 0.0f, p2 = 0.0f, p3 = 0.0f;
#pragma unroll
    for (int j = 0; j < PSI; j += 4) {
        p0 = fmaf(fmaxf(fmaf(x, sw1[j+0], sb1[j+0]), 0.0f), sw2[j+0], p0);
        p1 = fmaf(fmaxf(fmaf(x, sw1[j+1], sb1[j+1]), 0.0f), sw2[j+1], p1);
        p2 = fmaf(fmaxf(fmaf(x, sw1[j+2], sb1[j+2]), 0.0f), sw2[j+2], p2);
        p3 = fmaf(fmaxf(fmaf(x, sw1[j+3], sb1[j+3]), 0.0f), sw2[j+3], p3);
    }
    float acc = sb2 + (p0 + p1) + (p2 + p3);
    g_t[i] = acc * acc;
}

// ---------------------------------------------------------------------------
// Kernel 3: row score.  s[r] = sum_n adj[r,n]^2 * t[n]
// Grid-stride rows, grid 1184 (8 blocks/SM).  256-bit loads (LDG.E.256):
// one v8 adj load (evict-first) + one v8 t load per iteration — half the
// LDG issue count of the float4 version.  PDL secondary.
// ---------------------------------------------------------------------------
__global__ __launch_bounds__(256, 8) void k_row_score(const float* __restrict__ adj) {
    __shared__ float warp_sum[8];

    cudaGridDependencySynchronize();   // g_t ready

    for (int row = blockIdx.x; row < N_NODES; row += GRID_RS) {
        const float* __restrict__ a = adj + (size_t)row * N_NODES;
        float acc = 0.0f;
#pragma unroll 1
        for (int i = threadIdx.x; i < NV8; i += 256) {
            float av[8], tw[8];
            ldg256_cs(a + i * 8, av);
            ldg256_nc(g_t + i * 8, tw);
#pragma unroll
            for (int k = 0; k < 8; k++)
                acc = fmaf(av[k] * av[k], tw[k], acc);
        }
#pragma unroll
        for (int off = 16; off > 0; off >>= 1)
            acc += __shfl_down_sync(0xffffffffu, acc, off);
        if ((threadIdx.x & 31) == 0) warp_sum[threadIdx.x >> 5] = acc;
        __syncthreads();
        if (threadIdx.x < 8) {
            float v = warp_sum[threadIdx.x];
#pragma unroll
            for (int off = 4; off > 0; off >>= 1)
                v += __shfl_down_sync(0xffu, v, off);
            if (threadIdx.x == 0) g_s[row] = v;
        }
        __syncthreads();   // warp_sum reuse next row
    }
}

// ---------------------------------------------------------------------------
// Kernel 4: gather per-edge output (g_s is L2-hot).  PDL secondary.
// ---------------------------------------------------------------------------
__global__ __launch_bounds__(256) void k_gather(const int* __restrict__ src_nodes,
                                                float* __restrict__ out, int E) {
    int e = blockIdx.x * 256 + threadIdx.x;
    cudaGridDependencySynchronize();   // g_s ready
    if (e < E) out[e] = g_s[src_nodes[e]];
}

// ---------------------------------------------------------------------------
// launch helper: PDL launch (programmatic stream serialization)
// ---------------------------------------------------------------------------
template <typename... Args>
static inline void launch_pdl(void (*kern)(Args...), dim3 grid, dim3 block,
                              Args... args) {
    cudaLaunchAttribute attr[1];
    attr[0].id = cudaLaunchAttributeProgrammaticStreamSerialization;
    attr[0].val.programmaticStreamSerializationAllowed = 1;
    cudaLaunchConfig_t cfg{};
    cfg.gridDim = grid;
    cfg.blockDim = block;
    cfg.dynamicSmemBytes = 0;
    cfg.stream = 0;
    cfg.attrs = attr;
    cfg.numAttrs = 1;
    cudaLaunchKernelEx(&cfg, kern, args...);
}

// ---------------------------------------------------------------------------
// launch
// Inputs (metadata order): col, values, adj, src_nodes,
//                          w1e, b1e, w2e, b2e, w1n, b1n, w2n, b2n
// ---------------------------------------------------------------------------
extern "C" void kernel_launch(void* const* d_in, const int* in_sizes, int n_in,
                              void* d_out, int out_size) {
    const int*   col       = (const int*)d_in[0];
    const float* values    = (const float*)d_in[1];
    const float* adj       = (const float*)d_in[2];
    const int*   src_nodes = (const int*)d_in[3];
    const float* w1e = (const float*)d_in[4];
    const float* b1e = (const float*)d_in[5];
    const float* w2e = (const float*)d_in[6];
    const float* b2e = (const float*)d_in[7];
    const float* w1n = (const float*)d_in[8];
    const float* b1n = (const float*)d_in[9];
    const float* w2n = (const float*)d_in[10];
    const float* b2n = (const float*)d_in[11];
    float* out = (float*)d_out;

    const int nnz = in_sizes[0];   // 262144
    const int E   = in_sizes[3];   // 32768

    // prefetch first (triggers immediately, so scatter overlaps it)
    k_prefetch<<<512, 256>>>(adj);

    // scatter: PDL, NO grid-sync inside (independent of prefetch)
    launch_pdl(k_edge_scatter, dim3((nnz + 255) / 256), dim3(256),
               col, values, w1e, b1e, w2e, b2e, nnz);

    // dependents: PDL with grid-sync
    launch_pdl(k_node_mlp, dim3((N_NODES + 511) / 512), dim3(512),
               w1n, b1n, w2n, b2n);
    launch_pdl(k_row_score, dim3(GRID_RS), dim3(256), adj);
    launch_pdl(k_gather, dim3((E + 255) / 256), dim3(256),
               src_nodes, out, E);
}